// round 11
// baseline (speedup 1.0000x reference)
#include <cuda_runtime.h>
#include <cstdint>

#define N_NODES 100000
#define N_EDGES 3200000

// Scratch (static device globals — no allocation allowed).
// g_acc is zero at module load; node_kernel self-resets it after reading, so
// every invocation (correctness run + each graph replay) sees zeros.
__device__ float2 g_acc[N_NODES];   // .x = denom, .y = numer
__device__ float  g_inv[N_NODES];   // dense reciprocal for the normalize pass

__device__ __forceinline__ void red_add_v2(float2* addr, float a, float b) {
    asm volatile("red.global.add.v2.f32 [%0], {%1, %2};"
                 :: "l"(addr), "f"(a), "f"(b) : "memory");
}

// Edge pass, 4 lanes per edge (64 edges per 256-thread block):
//  - each lane loads ONE float4 of its edge's ea row  -> fully coalesced
//    (512B per warp-instruction instead of 64B-strided: 4x fewer L1tex
//     wavefronts on the 205MB ea stream)
//  - partial ea.We dot per lane, shfl_xor butterfly reduce within the group
//  - lane 0 of each group: x gathers, leaky_relu, pp store, exp, red.v2
__global__ void __launch_bounds__(256) edge_kernel(
                            const float* __restrict__ x,
                            const int*   __restrict__ ei,
                            const float* __restrict__ ea,
                            const float* __restrict__ Wn,
                            const float* __restrict__ We,
                            float* __restrict__ pp_out)
{
    __shared__ float sWe[32];
    __shared__ float sWn[4];
    int t = threadIdx.x;
    if (t < 32)       sWe[t]      = We[t];
    else if (t < 36)  sWn[t - 32] = Wn[t - 32];
    __syncthreads();

    int g   = t >> 2;          // edge group within block: 0..63
    int sub = t & 3;           // float4 chunk within edge: 0..3
    int e   = blockIdx.x * 64 + g;

    // Coalesced stream load: thread reads float4 #sub of edge e.
    float4 v = __ldcs((const float4*)ea + (size_t)e * 4 + sub);

    // Partial dot with We rows sub*4 .. sub*4+3 (We row-major [16,2]).
    const float* w = sWe + sub * 8;
    float p0 = v.x * w[0] + v.y * w[2] + v.z * w[4] + v.w * w[6];
    float p1 = v.x * w[1] + v.y * w[3] + v.z * w[5] + v.w * w[7];

    // Butterfly reduce within the 4-lane group (xor 1, then 2).
    p0 += __shfl_xor_sync(0xFFFFFFFFu, p0, 1);
    p1 += __shfl_xor_sync(0xFFFFFFFFu, p1, 1);
    p0 += __shfl_xor_sync(0xFFFFFFFFu, p0, 2);
    p1 += __shfl_xor_sync(0xFFFFFFFFu, p1, 2);

    if (sub == 0) {
        int src = ei[e];                 // 8 active lanes/warp, consecutive e -> coalesced
        int dst = ei[N_EDGES + e];
        float xs = __ldg(x + src);
        float xd = __ldg(x + dst);

        p0 += xs * sWn[0] + xd * sWn[2];
        p1 += xs * sWn[1] + xd * sWn[3];

        // leaky_relu(., 0.2)
        p0 = (p0 > 0.0f) ? p0 : 0.2f * p0;
        p1 = (p1 > 0.0f) ? p1 : 0.2f * p1;

        ((float2*)pp_out)[e] = make_float2(p0, p1);   // L2-resident for attn pass

        float ex = __expf(p0 - p1);   // softmax shift-invariant; |score| << 88
        red_add_v2(&g_acc[dst], ex, ex * xs);
    }
}

// out[i] = W0 * numer * inv_denom ; stash inv_denom; reset g_acc for next call.
__global__ void node_kernel(float* __restrict__ out, const float* __restrict__ W) {
    int i = blockIdx.x * blockDim.x + threadIdx.x;
    if (i < N_NODES) {
        float2 a = g_acc[i];
        float inv = 1.0f / (a.x + 1e-16f);
        out[i] = W[0] * a.y * inv;
        g_inv[i] = inv;
        g_acc[i] = make_float2(0.0f, 0.0f);
    }
}

// Normalize pass, 4 edges/thread (proven shape): re-read pair_pred,
// recompute ex, gather dense g_inv, write attn once (streaming).
__global__ void __launch_bounds__(256) attn_kernel(
                            const int*   __restrict__ ei,
                            const float* __restrict__ pp,
                            float* __restrict__ attn)
{
    int e = (blockIdx.x * blockDim.x + threadIdx.x) * 4;
    if (e >= N_EDGES) return;

    int4 d = *(const int4*)(ei + N_EDGES + e);

    // Issue the 4 random gathers early (longest latency).
    float i0 = __ldg(g_inv + d.x);
    float i1 = __ldg(g_inv + d.y);
    float i2 = __ldg(g_inv + d.z);
    float i3 = __ldg(g_inv + d.w);

    float4 pa = *(const float4*)(pp + 2 * (size_t)e);      // edges e, e+1
    float4 pb = *(const float4*)(pp + 2 * (size_t)e + 4);  // edges e+2, e+3

    float ex0 = __expf(pa.x - pa.y);
    float ex1 = __expf(pa.z - pa.w);
    float ex2 = __expf(pb.x - pb.y);
    float ex3 = __expf(pb.z - pb.w);

    __stcs((float4*)(attn + e),
           make_float4(ex0 * i0, ex1 * i1, ex2 * i2, ex3 * i3));
}

extern "C" void kernel_launch(void* const* d_in, const int* in_sizes, int n_in,
                              void* d_out, int out_size)
{
    // Resolve inputs by element count (all distinct) — robust to ordering.
    const float* x  = nullptr;   // 100000
    const int*   ei = nullptr;   // 6400000 (int32)
    const float* ea = nullptr;   // 51200000
    const float* W  = nullptr;   // 1
    const float* Wn = nullptr;   // 4
    const float* We = nullptr;   // 32
    for (int i = 0; i < n_in; i++) {
        switch (in_sizes[i]) {
            case N_NODES:      x  = (const float*)d_in[i]; break;
            case 2 * N_EDGES:  ei = (const int*)d_in[i];   break;
            case 16 * N_EDGES: ea = (const float*)d_in[i]; break;
            case 1:            W  = (const float*)d_in[i]; break;
            case 4:            Wn = (const float*)d_in[i]; break;
            case 32:           We = (const float*)d_in[i]; break;
        }
    }

    float* out  = (float*)d_out;                 // [N]
    float* attn = out + N_NODES;                 // [E]
    float* pp   = out + N_NODES + N_EDGES;       // [E,2]

    edge_kernel<<<N_EDGES / 64, 256>>>(x, ei, ea, Wn, We, pp);
    node_kernel<<<(N_NODES + 255) / 256, 256>>>(out, W);
    attn_kernel<<<N_EDGES / (256 * 4), 256>>>(ei, pp, attn);
}

// round 12
// speedup vs baseline: 1.0760x; 1.0760x over previous
#include <cuda_runtime.h>
#include <cstdint>

#define N_NODES 100000
#define N_EDGES 3200000

// Scratch (static device globals — no allocation allowed).
// g_acc is zero at module load; node_kernel self-resets it after reading, so
// every invocation (correctness run + each graph replay) sees zeros.
__device__ float2 g_acc[N_NODES];   // .x = denom, .y = numer
__device__ float  g_inv[N_NODES];   // dense reciprocal for the normalize pass

__device__ __forceinline__ void red_add_v2(float2* addr, float a, float b) {
    asm volatile("red.global.add.v2.f32 [%0], {%1, %2};"
                 :: "l"(addr), "f"(a), "f"(b) : "memory");
}

// Edge pass, 256 edges per 256-thread block, 1 edge/thread compute:
//  Phase A: stage the block's ea tile (256 edges x 16 floats = 16KB) into
//           smem with fully-coalesced float4 loads (4/thread). This removes
//           the 64B-strided LDG pattern that made ea consume ~40% of all
//           L1tex wavefronts in the R10 kernel.
//  Phase B: per-edge compute identical to R10, reading ea from smem
//           (row stride 17 words -> conflict-free LDS).
__global__ void __launch_bounds__(256) edge_kernel(
                            const float* __restrict__ x,
                            const int*   __restrict__ ei,
                            const float* __restrict__ ea,
                            const float* __restrict__ Wn,
                            const float* __restrict__ We,
                            float* __restrict__ pp_out)
{
    __shared__ float s_ea[256 * 17];   // [edge][word], padded row
    __shared__ float sWe[32];
    __shared__ float sWn[4];

    int t = threadIdx.x;
    if (t < 32)       sWe[t]      = We[t];
    else if (t < 36)  sWn[t - 32] = Wn[t - 32];

    int base = blockIdx.x * 256;

    // Phase A: coalesced fill. float4 index f within tile; edge = f/4.
#pragma unroll
    for (int k = 0; k < 4; k++) {
        int f = k * 256 + t;
        float4 v = __ldcs((const float4*)ea + (size_t)base * 4 + f);
        float* p = s_ea + (f >> 2) * 17 + (f & 3) * 4;
        p[0] = v.x; p[1] = v.y; p[2] = v.z; p[3] = v.w;
    }
    __syncthreads();

    // Phase B: per-edge compute.
    int e = base + t;
    int src = ei[e];
    int dst = ei[N_EDGES + e];
    float xs = __ldg(x + src);
    float xd = __ldg(x + dst);

    float p0 = xs * sWn[0] + xd * sWn[2];
    float p1 = xs * sWn[1] + xd * sWn[3];

    const float* r = s_ea + t * 17;
#pragma unroll
    for (int w = 0; w < 16; w++) {
        float v = r[w];
        p0 += v * sWe[2 * w];
        p1 += v * sWe[2 * w + 1];
    }

    // leaky_relu(., 0.2)
    p0 = (p0 > 0.0f) ? p0 : 0.2f * p0;
    p1 = (p1 > 0.0f) ? p1 : 0.2f * p1;

    ((float2*)pp_out)[e] = make_float2(p0, p1);   // L2-resident for attn pass

    float ex = __expf(p0 - p1);   // softmax shift-invariant; |score| << 88
    red_add_v2(&g_acc[dst], ex, ex * xs);
}

// out[i] = W0 * numer * inv_denom ; stash inv_denom; reset g_acc for next call.
__global__ void node_kernel(float* __restrict__ out, const float* __restrict__ W) {
    int i = blockIdx.x * blockDim.x + threadIdx.x;
    if (i < N_NODES) {
        float2 a = g_acc[i];
        float inv = 1.0f / (a.x + 1e-16f);
        out[i] = W[0] * a.y * inv;
        g_inv[i] = inv;
        g_acc[i] = make_float2(0.0f, 0.0f);
    }
}

// Normalize pass, 4 edges/thread (proven shape): re-read pair_pred,
// recompute ex, gather dense g_inv, write attn once (streaming).
__global__ void __launch_bounds__(256) attn_kernel(
                            const int*   __restrict__ ei,
                            const float* __restrict__ pp,
                            float* __restrict__ attn)
{
    int e = (blockIdx.x * blockDim.x + threadIdx.x) * 4;
    if (e >= N_EDGES) return;

    int4 d = *(const int4*)(ei + N_EDGES + e);

    // Issue the 4 random gathers early (longest latency).
    float i0 = __ldg(g_inv + d.x);
    float i1 = __ldg(g_inv + d.y);
    float i2 = __ldg(g_inv + d.z);
    float i3 = __ldg(g_inv + d.w);

    float4 pa = *(const float4*)(pp + 2 * (size_t)e);      // edges e, e+1
    float4 pb = *(const float4*)(pp + 2 * (size_t)e + 4);  // edges e+2, e+3

    float ex0 = __expf(pa.x - pa.y);
    float ex1 = __expf(pa.z - pa.w);
    float ex2 = __expf(pb.x - pb.y);
    float ex3 = __expf(pb.z - pb.w);

    __stcs((float4*)(attn + e),
           make_float4(ex0 * i0, ex1 * i1, ex2 * i2, ex3 * i3));
}

extern "C" void kernel_launch(void* const* d_in, const int* in_sizes, int n_in,
                              void* d_out, int out_size)
{
    // Resolve inputs by element count (all distinct) — robust to ordering.
    const float* x  = nullptr;   // 100000
    const int*   ei = nullptr;   // 6400000 (int32)
    const float* ea = nullptr;   // 51200000
    const float* W  = nullptr;   // 1
    const float* Wn = nullptr;   // 4
    const float* We = nullptr;   // 32
    for (int i = 0; i < n_in; i++) {
        switch (in_sizes[i]) {
            case N_NODES:      x  = (const float*)d_in[i]; break;
            case 2 * N_EDGES:  ei = (const int*)d_in[i];   break;
            case 16 * N_EDGES: ea = (const float*)d_in[i]; break;
            case 1:            W  = (const float*)d_in[i]; break;
            case 4:            Wn = (const float*)d_in[i]; break;
            case 32:           We = (const float*)d_in[i]; break;
        }
    }

    float* out  = (float*)d_out;                 // [N]
    float* attn = out + N_NODES;                 // [E]
    float* pp   = out + N_NODES + N_EDGES;       // [E,2]

    edge_kernel<<<N_EDGES / 256, 256>>>(x, ei, ea, Wn, We, pp);
    node_kernel<<<(N_NODES + 255) / 256, 256>>>(out, W);
    attn_kernel<<<N_EDGES / (256 * 4), 256>>>(ei, pp, attn);
}

// round 14
// speedup vs baseline: 1.1338x; 1.0537x over previous
#include <cuda_runtime.h>
#include <cstdint>

#define N_NODES 100000
#define N_EDGES 3200000

// Scratch (static device globals — no allocation allowed).
// g_acc is zero at module load; node_kernel self-resets it after reading, so
// every invocation (correctness run + each graph replay) sees zeros.
__device__ float2 g_acc[N_NODES];   // .x = denom, .y = numer
__device__ float  g_inv[N_NODES];   // dense reciprocal for the normalize pass

__device__ __forceinline__ void red_add_v2(float2* addr, float a, float b) {
    asm volatile("red.global.add.v2.f32 [%0], {%1, %2};"
                 :: "l"(addr), "f"(a), "f"(b) : "memory");
}

// Edge pass, pair-interleaved ea loads + 1-edge/thread tail:
//  Threads 2j,2j+1 jointly load edges (base+2j, base+2j+1): load k of
//  thread (pair p, parity r) reads float4 chunk 2k+r of the pair's 128B
//  region -> lanes 2j,2j+1 hit ADJACENT float4s = one 32B sector/pair:
//  16 sectors per warp-instr (optimal) instead of 32 (R10's 64B stride).
//  4 shfl_xor(.,1) complete both edges' partial dots; thread r finalizes
//  edge base+2p+r with the same tail as the proven R10 kernel.
__global__ void __launch_bounds__(256) edge_kernel(
                            const float* __restrict__ x,
                            const int*   __restrict__ ei,
                            const float* __restrict__ ea,
                            const float* __restrict__ Wn,
                            const float* __restrict__ We,
                            float* __restrict__ pp_out)
{
    __shared__ float sWe[32];
    __shared__ float sWn[4];
    int t = threadIdx.x;
    if (t < 32)       sWe[t]      = We[t];
    else if (t < 36)  sWn[t - 32] = Wn[t - 32];
    __syncthreads();

    int p = t >> 1;            // pair index within block (0..127)
    int r = t & 1;             // parity: which edge of the pair this thread finalizes

    int base  = blockIdx.x * 256;
    size_t b4 = (size_t)base * 4 + (size_t)p * 8 + r;   // float4 index of chunk k=0

    // Pair-interleaved coalesced loads: chunk 2k+r of the pair's 8 float4s.
    float4 v0 = __ldcs((const float4*)ea + b4 + 0);   // edge A, pos r
    float4 v1 = __ldcs((const float4*)ea + b4 + 2);   // edge A, pos 2+r
    float4 v2 = __ldcs((const float4*)ea + b4 + 4);   // edge B, pos r
    float4 v3 = __ldcs((const float4*)ea + b4 + 6);   // edge B, pos 2+r

    // Partial dots. Position m uses We rows 4m..4m+3 = sWe[8m + 2i (+1)].
    const float* wa = sWe + 8 * r;          // pos r
    const float* wb = sWe + 16 + 8 * r;     // pos 2+r

    float p0A = v0.x * wa[0] + v0.y * wa[2] + v0.z * wa[4] + v0.w * wa[6]
              + v1.x * wb[0] + v1.y * wb[2] + v1.z * wb[4] + v1.w * wb[6];
    float p1A = v0.x * wa[1] + v0.y * wa[3] + v0.z * wa[5] + v0.w * wa[7]
              + v1.x * wb[1] + v1.y * wb[3] + v1.z * wb[5] + v1.w * wb[7];
    float p0B = v2.x * wa[0] + v2.y * wa[2] + v2.z * wa[4] + v2.w * wa[6]
              + v3.x * wb[0] + v3.y * wb[2] + v3.z * wb[4] + v3.w * wb[6];
    float p1B = v2.x * wa[1] + v2.y * wa[3] + v2.z * wa[5] + v2.w * wa[7]
              + v3.x * wb[1] + v3.y * wb[3] + v3.z * wb[5] + v3.w * wb[7];

    // Pair reduce: after these, both threads hold the full sums of both edges.
    p0A += __shfl_xor_sync(0xFFFFFFFFu, p0A, 1);
    p1A += __shfl_xor_sync(0xFFFFFFFFu, p1A, 1);
    p0B += __shfl_xor_sync(0xFFFFFFFFu, p0B, 1);
    p1B += __shfl_xor_sync(0xFFFFFFFFu, p1B, 1);

    // Thread r finalizes edge base + 2p + r  ->  e = base + t (coalesced tail).
    float p0 = r ? p0B : p0A;
    float p1 = r ? p1B : p1A;
    int e = base + t;

    int src = ei[e];
    int dst = ei[N_EDGES + e];
    float xs = __ldg(x + src);
    float xd = __ldg(x + dst);

    p0 += xs * sWn[0] + xd * sWn[2];
    p1 += xs * sWn[1] + xd * sWn[3];

    // leaky_relu(., 0.2)
    p0 = (p0 > 0.0f) ? p0 : 0.2f * p0;
    p1 = (p1 > 0.0f) ? p1 : 0.2f * p1;

    ((float2*)pp_out)[e] = make_float2(p0, p1);   // L2-resident for attn pass

    float ex = __expf(p0 - p1);   // softmax shift-invariant; |score| << 88
    red_add_v2(&g_acc[dst], ex, ex * xs);
}

// out[i] = W0 * numer * inv_denom ; stash inv_denom; reset g_acc for next call.
__global__ void node_kernel(float* __restrict__ out, const float* __restrict__ W) {
    int i = blockIdx.x * blockDim.x + threadIdx.x;
    if (i < N_NODES) {
        float2 a = g_acc[i];
        float inv = 1.0f / (a.x + 1e-16f);
        out[i] = W[0] * a.y * inv;
        g_inv[i] = inv;
        g_acc[i] = make_float2(0.0f, 0.0f);
    }
}

// Normalize pass, 4 edges/thread (proven shape): re-read pair_pred,
// recompute ex, gather dense g_inv, write attn once (streaming).
__global__ void __launch_bounds__(256) attn_kernel(
                            const int*   __restrict__ ei,
                            const float* __restrict__ pp,
                            float* __restrict__ attn)
{
    int e = (blockIdx.x * blockDim.x + threadIdx.x) * 4;
    if (e >= N_EDGES) return;

    int4 d = *(const int4*)(ei + N_EDGES + e);

    // Issue the 4 random gathers early (longest latency).
    float i0 = __ldg(g_inv + d.x);
    float i1 = __ldg(g_inv + d.y);
    float i2 = __ldg(g_inv + d.z);
    float i3 = __ldg(g_inv + d.w);

    float4 pa = *(const float4*)(pp + 2 * (size_t)e);      // edges e, e+1
    float4 pb = *(const float4*)(pp + 2 * (size_t)e + 4);  // edges e+2, e+3

    float ex0 = __expf(pa.x - pa.y);
    float ex1 = __expf(pa.z - pa.w);
    float ex2 = __expf(pb.x - pb.y);
    float ex3 = __expf(pb.z - pb.w);

    __stcs((float4*)(attn + e),
           make_float4(ex0 * i0, ex1 * i1, ex2 * i2, ex3 * i3));
}

extern "C" void kernel_launch(void* const* d_in, const int* in_sizes, int n_in,
                              void* d_out, int out_size)
{
    // Resolve inputs by element count (all distinct) — robust to ordering.
    const float* x  = nullptr;   // 100000
    const int*   ei = nullptr;   // 6400000 (int32)
    const float* ea = nullptr;   // 51200000
    const float* W  = nullptr;   // 1
    const float* Wn = nullptr;   // 4
    const float* We = nullptr;   // 32
    for (int i = 0; i < n_in; i++) {
        switch (in_sizes[i]) {
            case N_NODES:      x  = (const float*)d_in[i]; break;
            case 2 * N_EDGES:  ei = (const int*)d_in[i];   break;
            case 16 * N_EDGES: ea = (const float*)d_in[i]; break;
            case 1:            W  = (const float*)d_in[i]; break;
            case 4:            Wn = (const float*)d_in[i]; break;
            case 32:           We = (const float*)d_in[i]; break;
        }
    }

    float* out  = (float*)d_out;                 // [N]
    float* attn = out + N_NODES;                 // [E]
    float* pp   = out + N_NODES + N_EDGES;       // [E,2]

    edge_kernel<<<N_EDGES / 256, 256>>>(x, ei, ea, Wn, We, pp);
    node_kernel<<<(N_NODES + 255) / 256, 256>>>(out, W);
    attn_kernel<<<N_EDGES / (256 * 4), 256>>>(ei, pp, attn);
}

// round 15
// speedup vs baseline: 1.1410x; 1.0063x over previous
#include <cuda_runtime.h>
#include <cstdint>

#define N_NODES 100000
#define N_EDGES 3200000

// Scratch (static device globals — no allocation allowed).
// g_acc is zero at module load; node_kernel self-resets it after reading, so
// every invocation (correctness run + each graph replay) sees zeros.
__device__ float2 g_acc[N_NODES];   // .x = denom, .y = numer
__device__ float  g_inv[N_NODES];   // dense reciprocal for the normalize pass

// Weights in __constant__: reads go through the constant port (LDCU), NOT the
// L1tex pipe that LDS/LDG share — removes ~36 broadcast-LDS wavefronts/warp
// from the edge kernel. Filled per-launch via capturable D2D memcpys.
__constant__ float cWe[32];
__constant__ float cWn[4];
__constant__ float cW0[1];

__device__ __forceinline__ void red_add_v2(float2* addr, float a, float b) {
    asm volatile("red.global.add.v2.f32 [%0], {%1, %2};"
                 :: "l"(addr), "f"(a), "f"(b) : "memory");
}

// Edge pass, 1 edge/thread (R10-proven shape, weights from __constant__):
//  - pair_pred = leaky_relu([x_src, x_dst] @ Wn + ea @ We, 0.2) -> pp
//  - g_acc[dst] += (ex, ex * x[src])  via one red.v2; ex not stored.
__global__ void __launch_bounds__(256, 8) edge_kernel(
                            const float* __restrict__ x,
                            const int*   __restrict__ ei,
                            const float* __restrict__ ea,
                            float* __restrict__ pp_out)
{
    int e = blockIdx.x * blockDim.x + threadIdx.x;
    if (e >= N_EDGES) return;

    int src = ei[e];
    int dst = ei[N_EDGES + e];
    float xs = __ldg(x + src);
    float xd = __ldg(x + dst);

    // edge_attr is a pure stream — evict-first so it doesn't pollute L1/L2.
    const float4* ea4 = (const float4*)(ea + (size_t)e * 16);
    float4 v0 = __ldcs(ea4 + 0);
    float4 v1 = __ldcs(ea4 + 1);
    float4 v2 = __ldcs(ea4 + 2);
    float4 v3 = __ldcs(ea4 + 3);

    float p0 = xs * cWn[0] + xd * cWn[2];
    float p1 = xs * cWn[1] + xd * cWn[3];

    p0 += v0.x * cWe[0]  + v0.y * cWe[2]  + v0.z * cWe[4]  + v0.w * cWe[6];
    p1 += v0.x * cWe[1]  + v0.y * cWe[3]  + v0.z * cWe[5]  + v0.w * cWe[7];
    p0 += v1.x * cWe[8]  + v1.y * cWe[10] + v1.z * cWe[12] + v1.w * cWe[14];
    p1 += v1.x * cWe[9]  + v1.y * cWe[11] + v1.z * cWe[13] + v1.w * cWe[15];
    p0 += v2.x * cWe[16] + v2.y * cWe[18] + v2.z * cWe[20] + v2.w * cWe[22];
    p1 += v2.x * cWe[17] + v2.y * cWe[19] + v2.z * cWe[21] + v2.w * cWe[23];
    p0 += v3.x * cWe[24] + v3.y * cWe[26] + v3.z * cWe[28] + v3.w * cWe[30];
    p1 += v3.x * cWe[25] + v3.y * cWe[27] + v3.z * cWe[29] + v3.w * cWe[31];

    // leaky_relu(., 0.2)
    p0 = (p0 > 0.0f) ? p0 : 0.2f * p0;
    p1 = (p1 > 0.0f) ? p1 : 0.2f * p1;

    ((float2*)pp_out)[e] = make_float2(p0, p1);   // L2-resident for attn pass

    float ex = __expf(p0 - p1);   // softmax shift-invariant; |score| << 88
    red_add_v2(&g_acc[dst], ex, ex * xs);
}

// out[i] = W0 * numer * inv_denom ; stash inv_denom; reset g_acc for next call.
__global__ void node_kernel(float* __restrict__ out) {
    int i = blockIdx.x * blockDim.x + threadIdx.x;
    if (i < N_NODES) {
        float2 a = g_acc[i];
        float inv = 1.0f / (a.x + 1e-16f);
        out[i] = cW0[0] * a.y * inv;
        g_inv[i] = inv;
        g_acc[i] = make_float2(0.0f, 0.0f);
    }
}

// Normalize pass, 4 edges/thread (proven shape): re-read pair_pred,
// recompute ex, gather dense g_inv, write attn once (streaming).
__global__ void __launch_bounds__(256) attn_kernel(
                            const int*   __restrict__ ei,
                            const float* __restrict__ pp,
                            float* __restrict__ attn)
{
    int e = (blockIdx.x * blockDim.x + threadIdx.x) * 4;
    if (e >= N_EDGES) return;

    int4 d = *(const int4*)(ei + N_EDGES + e);

    // Issue the 4 random gathers early (longest latency).
    float i0 = __ldg(g_inv + d.x);
    float i1 = __ldg(g_inv + d.y);
    float i2 = __ldg(g_inv + d.z);
    float i3 = __ldg(g_inv + d.w);

    float4 pa = *(const float4*)(pp + 2 * (size_t)e);      // edges e, e+1
    float4 pb = *(const float4*)(pp + 2 * (size_t)e + 4);  // edges e+2, e+3

    float ex0 = __expf(pa.x - pa.y);
    float ex1 = __expf(pa.z - pa.w);
    float ex2 = __expf(pb.x - pb.y);
    float ex3 = __expf(pb.z - pb.w);

    __stcs((float4*)(attn + e),
           make_float4(ex0 * i0, ex1 * i1, ex2 * i2, ex3 * i3));
}

extern "C" void kernel_launch(void* const* d_in, const int* in_sizes, int n_in,
                              void* d_out, int out_size)
{
    // Resolve inputs by element count (all distinct) — robust to ordering.
    const float* x  = nullptr;   // 100000
    const int*   ei = nullptr;   // 6400000 (int32)
    const float* ea = nullptr;   // 51200000
    const float* W  = nullptr;   // 1
    const float* Wn = nullptr;   // 4
    const float* We = nullptr;   // 32
    for (int i = 0; i < n_in; i++) {
        switch (in_sizes[i]) {
            case N_NODES:      x  = (const float*)d_in[i]; break;
            case 2 * N_EDGES:  ei = (const int*)d_in[i];   break;
            case 16 * N_EDGES: ea = (const float*)d_in[i]; break;
            case 1:            W  = (const float*)d_in[i]; break;
            case 4:            Wn = (const float*)d_in[i]; break;
            case 32:           We = (const float*)d_in[i]; break;
        }
    }

    float* out  = (float*)d_out;                 // [N]
    float* attn = out + N_NODES;                 // [E]
    float* pp   = out + N_NODES + N_EDGES;       // [E,2]

    // Capturable D2D copies into constant memory (no allocation, async).
    cudaMemcpyToSymbolAsync(cWe, We, 32 * sizeof(float), 0,
                            cudaMemcpyDeviceToDevice, 0);
    cudaMemcpyToSymbolAsync(cWn, Wn, 4 * sizeof(float), 0,
                            cudaMemcpyDeviceToDevice, 0);
    cudaMemcpyToSymbolAsync(cW0, W, sizeof(float), 0,
                            cudaMemcpyDeviceToDevice, 0);

    edge_kernel<<<(N_EDGES + 255) / 256, 256>>>(x, ei, ea, pp);
    node_kernel<<<(N_NODES + 255) / 256, 256>>>(out);
    attn_kernel<<<N_EDGES / (256 * 4), 256>>>(ei, pp, attn);
}

// round 16
// speedup vs baseline: 1.1656x; 1.0216x over previous
#include <cuda_runtime.h>
#include <cstdint>

#define N_NODES 100000
#define N_EDGES 3200000

// Scratch (static device globals — no allocation allowed).
// g_acc is zero at module load; node_kernel self-resets it after reading, so
// every invocation (correctness run + each graph replay) sees zeros.
__device__ float2 g_acc[N_NODES];   // .x = denom, .y = numer
__device__ float  g_inv[N_NODES];   // dense reciprocal for the normalize pass

__device__ __forceinline__ void red_add_v2(float2* addr, float a, float b) {
    asm volatile("red.global.add.v2.f32 [%0], {%1, %2};"
                 :: "l"(addr), "f"(a), "f"(b) : "memory");
}

// Edge pass, 1 edge/thread — EXACT R10 shape (empirically optimal after five
// alternatives: shuffle-split, smem staging, pair-interleave, constant-port
// all regressed). Weights in smem: broadcast LDS (floor 2) beats LDC (floor 8).
__global__ void __launch_bounds__(256) edge_kernel(
                            const float* __restrict__ x,
                            const int*   __restrict__ ei,
                            const float* __restrict__ ea,
                            const float* __restrict__ Wn,
                            const float* __restrict__ We,
                            float* __restrict__ pp_out)
{
    __shared__ float sWe[32];
    __shared__ float sWn[4];
    int t = threadIdx.x;
    if (t < 32)       sWe[t]      = We[t];
    else if (t < 36)  sWn[t - 32] = Wn[t - 32];
    __syncthreads();

    int e = blockIdx.x * blockDim.x + t;
    if (e >= N_EDGES) return;

    int src = ei[e];
    int dst = ei[N_EDGES + e];
    float xs = __ldg(x + src);
    float xd = __ldg(x + dst);

    // edge_attr is a pure stream — evict-first so it doesn't pollute L1/L2.
    const float4* ea4 = (const float4*)(ea + (size_t)e * 16);
    float4 v0 = __ldcs(ea4 + 0);
    float4 v1 = __ldcs(ea4 + 1);
    float4 v2 = __ldcs(ea4 + 2);
    float4 v3 = __ldcs(ea4 + 3);

    float p0 = xs * sWn[0] + xd * sWn[2];
    float p1 = xs * sWn[1] + xd * sWn[3];

    p0 += v0.x * sWe[0]  + v0.y * sWe[2]  + v0.z * sWe[4]  + v0.w * sWe[6];
    p1 += v0.x * sWe[1]  + v0.y * sWe[3]  + v0.z * sWe[5]  + v0.w * sWe[7];
    p0 += v1.x * sWe[8]  + v1.y * sWe[10] + v1.z * sWe[12] + v1.w * sWe[14];
    p1 += v1.x * sWe[9]  + v1.y * sWe[11] + v1.z * sWe[13] + v1.w * sWe[15];
    p0 += v2.x * sWe[16] + v2.y * sWe[18] + v2.z * sWe[20] + v2.w * sWe[22];
    p1 += v2.x * sWe[17] + v2.y * sWe[19] + v2.z * sWe[21] + v2.w * sWe[23];
    p0 += v3.x * sWe[24] + v3.y * sWe[26] + v3.z * sWe[28] + v3.w * sWe[30];
    p1 += v3.x * sWe[25] + v3.y * sWe[27] + v3.z * sWe[29] + v3.w * sWe[31];

    // leaky_relu(., 0.2)
    p0 = (p0 > 0.0f) ? p0 : 0.2f * p0;
    p1 = (p1 > 0.0f) ? p1 : 0.2f * p1;

    ((float2*)pp_out)[e] = make_float2(p0, p1);   // L2-resident for attn pass

    float ex = __expf(p0 - p1);   // softmax shift-invariant; |score| << 88
    red_add_v2(&g_acc[dst], ex, ex * xs);
}

// out[i] = W0 * numer * inv_denom ; stash inv_denom; reset g_acc for next call.
__global__ void node_kernel(float* __restrict__ out, const float* __restrict__ W) {
    int i = blockIdx.x * blockDim.x + threadIdx.x;
    if (i < N_NODES) {
        float2 a = g_acc[i];
        float inv = 1.0f / (a.x + 1e-16f);
        out[i] = W[0] * a.y * inv;
        g_inv[i] = inv;
        g_acc[i] = make_float2(0.0f, 0.0f);
    }
}

// Normalize pass, 8 edges/thread: front-batch 8 independent random gathers
// plus 4 stream loads (MLP ~14) to push the L1tex wavefront pipe toward its
// ceiling (attn is latency-bound at 4 edges/thread: nothing above 60%).
__global__ void __launch_bounds__(256) attn_kernel(
                            const int*   __restrict__ ei,
                            const float* __restrict__ pp,
                            float* __restrict__ attn)
{
    int e = (blockIdx.x * blockDim.x + threadIdx.x) * 8;
    if (e >= N_EDGES) return;   // N_EDGES % 8 == 0: full 8-packs only

    int4 da = *(const int4*)(ei + N_EDGES + e);
    int4 db = *(const int4*)(ei + N_EDGES + e + 4);

    // Issue all 8 random gathers early (longest latency, independent).
    float i0 = __ldg(g_inv + da.x);
    float i1 = __ldg(g_inv + da.y);
    float i2 = __ldg(g_inv + da.z);
    float i3 = __ldg(g_inv + da.w);
    float i4 = __ldg(g_inv + db.x);
    float i5 = __ldg(g_inv + db.y);
    float i6 = __ldg(g_inv + db.z);
    float i7 = __ldg(g_inv + db.w);

    float4 pa = *(const float4*)(pp + 2 * (size_t)e);       // edges e..e+1
    float4 pb = *(const float4*)(pp + 2 * (size_t)e + 4);   // e+2..e+3
    float4 pc = *(const float4*)(pp + 2 * (size_t)e + 8);   // e+4..e+5
    float4 pd = *(const float4*)(pp + 2 * (size_t)e + 12);  // e+6..e+7

    float ex0 = __expf(pa.x - pa.y);
    float ex1 = __expf(pa.z - pa.w);
    float ex2 = __expf(pb.x - pb.y);
    float ex3 = __expf(pb.z - pb.w);
    float ex4 = __expf(pc.x - pc.y);
    float ex5 = __expf(pc.z - pc.w);
    float ex6 = __expf(pd.x - pd.y);
    float ex7 = __expf(pd.z - pd.w);

    __stcs((float4*)(attn + e),
           make_float4(ex0 * i0, ex1 * i1, ex2 * i2, ex3 * i3));
    __stcs((float4*)(attn + e + 4),
           make_float4(ex4 * i4, ex5 * i5, ex6 * i6, ex7 * i7));
}

extern "C" void kernel_launch(void* const* d_in, const int* in_sizes, int n_in,
                              void* d_out, int out_size)
{
    // Resolve inputs by element count (all distinct) — robust to ordering.
    const float* x  = nullptr;   // 100000
    const int*   ei = nullptr;   // 6400000 (int32)
    const float* ea = nullptr;   // 51200000
    const float* W  = nullptr;   // 1
    const float* Wn = nullptr;   // 4
    const float* We = nullptr;   // 32
    for (int i = 0; i < n_in; i++) {
        switch (in_sizes[i]) {
            case N_NODES:      x  = (const float*)d_in[i]; break;
            case 2 * N_EDGES:  ei = (const int*)d_in[i];   break;
            case 16 * N_EDGES: ea = (const float*)d_in[i]; break;
            case 1:            W  = (const float*)d_in[i]; break;
            case 4:            Wn = (const float*)d_in[i]; break;
            case 32:           We = (const float*)d_in[i]; break;
        }
    }

    float* out  = (float*)d_out;                 // [N]
    float* attn = out + N_NODES;                 // [E]
    float* pp   = out + N_NODES + N_EDGES;       // [E,2]

    edge_kernel<<<(N_EDGES + 255) / 256, 256>>>(x, ei, ea, Wn, We, pp);
    node_kernel<<<(N_NODES + 255) / 256, 256>>>(out, W);
    attn_kernel<<<(N_EDGES / 8 + 255) / 256, 256>>>(ei, pp, attn);
}